// round 7
// baseline (speedup 1.0000x reference)
#include <cuda_runtime.h>
#include <cuda_bf16.h>
#include <cstdint>

#define D 128
#define MAX_N    150016
#define MAX_OUT  50048
#define MAX_E    500000
#define SCAN_CHUNK 4096

// ---- device scratch (static: no runtime allocation allowed) ----
__device__ float g_deg[MAX_N];
__device__ int   g_cnt[MAX_OUT];
__device__ int   g_off[MAX_OUT + 1];   // chunk-LOCAL exclusive offsets
__device__ int   g_cursor[MAX_OUT];    // chunk-LOCAL cursors
__device__ int   g_bsum[64];           // per-chunk totals
__device__ int   g_bpre[64];           // exclusive chunk prefix
__device__ int2  g_epack[MAX_E];       // (row, coef) packed 8B
__device__ float g_agg[(size_t)MAX_OUT * D];
__device__ uint2 g_wf_h[8 * 16 * 32];  // W bf16-hi mma fragments [ks][nt][lane]
__device__ uint2 g_wf_l[8 * 16 * 32];  // W bf16-lo fragments

// ---- helpers ----
__device__ __forceinline__ uint16_t f2bf(float f) {
    __nv_bfloat16 h = __float2bfloat16_rn(f);
    return *reinterpret_cast<uint16_t*>(&h);
}
__device__ __forceinline__ float bf2f(uint16_t u) {
    __nv_bfloat16 h = *reinterpret_cast<__nv_bfloat16*>(&u);
    return __bfloat162float(h);
}
__device__ __forceinline__ uint32_t pack2(uint16_t lo, uint16_t hi) {
    return (uint32_t)lo | ((uint32_t)hi << 16);
}

#define MMA_BF16(ac, a, b0, b1)                                              \
    asm volatile(                                                            \
        "mma.sync.aligned.m16n8k16.row.col.f32.bf16.bf16.f32 "               \
        "{%0,%1,%2,%3}, {%4,%5,%6,%7}, {%8,%9}, {%0,%1,%2,%3};"              \
        : "+f"((ac)[0]), "+f"((ac)[1]), "+f"((ac)[2]), "+f"((ac)[3])         \
        : "r"((a)[0]), "r"((a)[1]), "r"((a)[2]), "r"((a)[3]),                \
          "r"(b0), "r"(b1))

#define LDSM_X4(r, addr)                                                     \
    asm volatile(                                                            \
        "ldmatrix.sync.aligned.m8n8.x4.shared.b16 {%0,%1,%2,%3}, [%4];"      \
        : "=r"((r)[0]), "=r"((r)[1]), "=r"((r)[2]), "=r"((r)[3])             \
        : "r"(addr))

// ---------------------------------------------------------------
// W fragment prep (device fn, folded into init_kernel)
// ---------------------------------------------------------------
__device__ __forceinline__ void wprep_one(const float* __restrict__ Wm, int idx) {
    int lane = idx & 31, nt = (idx >> 5) & 15, ks = idx >> 9;
    int g = lane >> 2, t = lane & 3;
    int n  = nt * 8 + g;
    int k0 = ks * 16 + 2 * t;
    float w00 = Wm[(k0 + 0) * D + n];
    float w01 = Wm[(k0 + 1) * D + n];
    float w10 = Wm[(k0 + 8) * D + n];
    float w11 = Wm[(k0 + 9) * D + n];
    uint16_t h00 = f2bf(w00), h01 = f2bf(w01), h10 = f2bf(w10), h11 = f2bf(w11);
    uint16_t l00 = f2bf(w00 - bf2f(h00)), l01 = f2bf(w01 - bf2f(h01));
    uint16_t l10 = f2bf(w10 - bf2f(h10)), l11 = f2bf(w11 - bf2f(h11));
    g_wf_h[idx] = make_uint2(pack2(h00, h01), pack2(h10, h11));
    g_wf_l[idx] = make_uint2(pack2(l00, l01), pack2(l10, l11));
}

// ---------------------------------------------------------------
// K0: init deg=1, zero counts, build W fragments (idle threads)
// ---------------------------------------------------------------
__global__ void init_kernel(const float* __restrict__ Wm, int n_tot, int n_out) {
    int i = blockIdx.x * blockDim.x + threadIdx.x;
    if (i < n_tot) g_deg[i] = 1.0f;
    if (i < n_out) g_cnt[i] = 0;
    if (i < 8 * 16 * 32) wprep_one(Wm, i);
}

// ---------------------------------------------------------------
// K1: degree accumulation + dest histogram
//     vectorized: each thread owns 4 consecutive edges via int4/float4
//     (coalesced loads + 4x MLP on the atomic chains)
// ---------------------------------------------------------------
__global__ void degcnt_kernel(const int* __restrict__ ei,
                              const float* __restrict__ ew, int n_edge,
                              int n_tot, int n_out) {
    int e = (blockIdx.x * blockDim.x + threadIdx.x) * 4;
    if (e + 3 < n_edge) {
        int4   r4 = *(const int4*)&ei[e];
        int4   c4 = *(const int4*)&ei[e + n_edge];
        float4 w4 = *(const float4*)&ew[e];
        if ((unsigned)r4.x < (unsigned)n_tot) atomicAdd(&g_deg[r4.x], w4.x);
        if ((unsigned)r4.y < (unsigned)n_tot) atomicAdd(&g_deg[r4.y], w4.y);
        if ((unsigned)r4.z < (unsigned)n_tot) atomicAdd(&g_deg[r4.z], w4.z);
        if ((unsigned)r4.w < (unsigned)n_tot) atomicAdd(&g_deg[r4.w], w4.w);
        if ((unsigned)c4.x < (unsigned)n_out) atomicAdd(&g_cnt[c4.x], 1);
        if ((unsigned)c4.y < (unsigned)n_out) atomicAdd(&g_cnt[c4.y], 1);
        if ((unsigned)c4.z < (unsigned)n_out) atomicAdd(&g_cnt[c4.z], 1);
        if ((unsigned)c4.w < (unsigned)n_out) atomicAdd(&g_cnt[c4.w], 1);
    } else {
        for (int j = 0; j < 4; j++) {
            int k = e + j;
            if (k >= n_edge) break;
            int row = ei[k], col = ei[k + n_edge];
            if ((unsigned)row < (unsigned)n_tot) atomicAdd(&g_deg[row], ew[k]);
            if ((unsigned)col < (unsigned)n_out) atomicAdd(&g_cnt[col], 1);
        }
    }
}

// ---------------------------------------------------------------
// K2a: per-chunk LOCAL exclusive scan (4096 elems / 1024-thr block)
//      writes local offsets into g_off AND g_cursor; chunk total
//      into g_bsum. Also writes g_off[n] (local) if n in range.
// ---------------------------------------------------------------
__global__ __launch_bounds__(1024) void scanA_kernel(int n) {
    __shared__ int wsum[32];
    int t = threadIdx.x, lane = t & 31, wid = t >> 5;
    int base = blockIdx.x * SCAN_CHUNK + t * 4;
    int v0 = 0, v1 = 0, v2 = 0, v3 = 0;
    if (base + 3 < n) {
        int4 v = *(const int4*)&g_cnt[base];
        v0 = v.x; v1 = v.y; v2 = v.z; v3 = v.w;
    } else {
        if (base + 0 < n) v0 = g_cnt[base + 0];
        if (base + 1 < n) v1 = g_cnt[base + 1];
        if (base + 2 < n) v2 = g_cnt[base + 2];
        if (base + 3 < n) v3 = g_cnt[base + 3];
    }
    int tin = v0 + v1 + v2 + v3;
    int incl = tin;
    #pragma unroll
    for (int o = 1; o < 32; o <<= 1) {
        int s = __shfl_up_sync(0xffffffffu, incl, o);
        if (lane >= o) incl += s;
    }
    if (lane == 31) wsum[wid] = incl;
    __syncthreads();
    if (wid == 0) {
        int ws = wsum[lane];
        int winc = ws;
        #pragma unroll
        for (int o = 1; o < 32; o <<= 1) {
            int s = __shfl_up_sync(0xffffffffu, winc, o);
            if (lane >= o) winc += s;
        }
        wsum[lane] = winc - ws;
    }
    __syncthreads();
    int texcl = wsum[wid] + incl - tin;
    int e0 = texcl, e1 = e0 + v0, e2 = e1 + v1, e3 = e2 + v2;
    if (base + 0 < n) { g_off[base + 0] = e0; g_cursor[base + 0] = e0; }
    if (base + 1 < n) { g_off[base + 1] = e1; g_cursor[base + 1] = e1; }
    if (base + 2 < n) { g_off[base + 2] = e2; g_cursor[base + 2] = e2; }
    if (base + 3 < n) { g_off[base + 3] = e3; g_cursor[base + 3] = e3; }
    if (n >= base && n <= base + 3) {          // local sentinel at n
        int d = n - base;
        g_off[n] = (d == 0) ? e0 : (d == 1) ? e1 : (d == 2) ? e2 : e3;
    }
    if (t == 1023) g_bsum[blockIdx.x] = wsum[wid] + incl;   // chunk TOTAL
}

// ---------------------------------------------------------------
// K2b: 1-warp exclusive prefix over chunk totals -> g_bpre
// ---------------------------------------------------------------
__global__ void scanB_kernel(int nblk, int n) {
    int t = threadIdx.x;
    int v = (t < nblk) ? g_bsum[t] : 0;
    int incl = v;
    #pragma unroll
    for (int o = 1; o < 32; o <<= 1) {
        int s = __shfl_up_sync(0xffffffffu, incl, o);
        if (t >= o) incl += s;
    }
    if (t <= nblk) g_bpre[t] = incl - v;   // t==nblk -> grand total prefix
    if ((n % SCAN_CHUNK) == 0 && t == 0) g_off[n] = 0;  // boundary sentinel
}

// ---------------------------------------------------------------
// K3: CSR placement, vectorized 4 edges/thread (int4/float4 loads),
//     absolute slot = local cursor + chunk prefix
// ---------------------------------------------------------------
__global__ void scatter_kernel(const int* __restrict__ ei,
                               const float* __restrict__ ew, int n_edge,
                               int n_tot, int n_out) {
    int e = (blockIdx.x * blockDim.x + threadIdx.x) * 4;
    if (e + 3 < n_edge) {
        int4   r4 = *(const int4*)&ei[e];
        int4   c4 = *(const int4*)&ei[e + n_edge];
        float4 w4 = *(const float4*)&ew[e];
        int rr[4] = {r4.x, r4.y, r4.z, r4.w};
        int cc[4] = {c4.x, c4.y, c4.z, c4.w};
        float ww[4] = {w4.x, w4.y, w4.z, w4.w};
        #pragma unroll
        for (int j = 0; j < 4; j++) {
            if ((unsigned)rr[j] >= (unsigned)n_tot ||
                (unsigned)cc[j] >= (unsigned)n_out) continue;
            float c = ww[j] * rsqrtf(g_deg[rr[j]]);
            int p = atomicAdd(&g_cursor[cc[j]], 1) + g_bpre[cc[j] >> 12];
            g_epack[p] = make_int2(rr[j], __float_as_int(c));
        }
    } else {
        for (int j = 0; j < 4; j++) {
            int k = e + j;
            if (k >= n_edge) break;
            int row = ei[k], col = ei[k + n_edge];
            if ((unsigned)row >= (unsigned)n_tot ||
                (unsigned)col >= (unsigned)n_out) continue;
            float c = ew[k] * rsqrtf(g_deg[row]);
            int p = atomicAdd(&g_cursor[col], 1) + g_bpre[col >> 12];
            g_epack[p] = make_int2(row, __float_as_int(c));
        }
    }
}

// ---------------------------------------------------------------
// K4: warp-per-node gather:  agg[j,:] = sum_e coef_e * x[row_e,:]
//     absolute range = local off + chunk prefix
// ---------------------------------------------------------------
__global__ void gather_kernel(const float* __restrict__ x, int n_out) {
    int w = (blockIdx.x * blockDim.x + threadIdx.x) >> 5;
    int lane = threadIdx.x & 31;
    if (w >= n_out) return;
    int s = g_off[w]     + g_bpre[w >> 12];
    int e = g_off[w + 1] + g_bpre[(w + 1) >> 12];
    const float4* x4 = (const float4*)x;
    float4 acc = make_float4(0.f, 0.f, 0.f, 0.f);
    int i = s;
    for (; i + 4 <= e; i += 4) {
        int2 p0 = g_epack[i];
        int2 p1 = g_epack[i + 1];
        int2 p2 = g_epack[i + 2];
        int2 p3 = g_epack[i + 3];
        float4 v0 = x4[(size_t)p0.x * 32 + lane];
        float4 v1 = x4[(size_t)p1.x * 32 + lane];
        float4 v2 = x4[(size_t)p2.x * 32 + lane];
        float4 v3 = x4[(size_t)p3.x * 32 + lane];
        float c0 = __int_as_float(p0.y), c1 = __int_as_float(p1.y);
        float c2 = __int_as_float(p2.y), c3 = __int_as_float(p3.y);
        acc.x += c0 * v0.x + c1 * v1.x + c2 * v2.x + c3 * v3.x;
        acc.y += c0 * v0.y + c1 * v1.y + c2 * v2.y + c3 * v3.y;
        acc.z += c0 * v0.z + c1 * v1.z + c2 * v2.z + c3 * v3.z;
        acc.w += c0 * v0.w + c1 * v1.w + c2 * v2.w + c3 * v3.w;
    }
    for (; i < e; i++) {
        int2 p0 = g_epack[i];
        float4 v0 = x4[(size_t)p0.x * 32 + lane];
        float c0 = __int_as_float(p0.y);
        acc.x += c0 * v0.x; acc.y += c0 * v0.y;
        acc.z += c0 * v0.z; acc.w += c0 * v0.w;
    }
    ((float4*)g_agg)[(size_t)w * 32 + lane] = acc;
}

// ---------------------------------------------------------------
// K5: tensor-core GEMM  out = relu(agg @ W + b)   [R4/R6-proven]
//   block = 128 rows x 128 cols, 8 warps (16 rows each)
//   bf16 2-way split: acc = Ah*Wh + Ah*Wl + Al*Wh  (fp32 accum)
//   smem: Ah/Al (69.6 KB) + staged W fragments (64 KB) = 132 KB
// ---------------------------------------------------------------
#define A_STRIDE 136

__global__ __launch_bounds__(256) void mma_gemm_kernel(const float* __restrict__ bias,
                                                       float* __restrict__ out,
                                                       int n_rows) {
    extern __shared__ char smem[];
    uint16_t* Ah = (uint16_t*)smem;                         // 34816 B
    uint16_t* Al = Ah + 128 * A_STRIDE;                     // +34816 B
    uint2*    Wfh = (uint2*)(smem + 2 * 128 * A_STRIDE * 2);// +32768 B
    uint2*    Wfl = Wfh + 4096;                             // +32768 B

    int tid = threadIdx.x;
    int w = tid >> 5, lane = tid & 31;
    int g = lane >> 2, t = lane & 3;
    int row0 = blockIdx.x * 128;

    // ---- stage W fragments ----
    #pragma unroll
    for (int i = tid; i < 4096; i += 256) {
        Wfh[i] = g_wf_h[i];
        Wfl[i] = g_wf_l[i];
    }

    // ---- stage A: load fp32 agg, split to bf16 hi/lo in smem ----
    #pragma unroll
    for (int i = 0; i < 16; i++) {
        int idx4 = tid + i * 256;          // 0..4095
        int r  = idx4 >> 5;                // 0..127
        int c4 = idx4 & 31;                // 0..31
        float4 v = make_float4(0.f, 0.f, 0.f, 0.f);
        if (row0 + r < n_rows)
            v = *(const float4*)&g_agg[(size_t)(row0 + r) * D + c4 * 4];
        uint16_t h0 = f2bf(v.x), h1 = f2bf(v.y), h2 = f2bf(v.z), h3 = f2bf(v.w);
        uint16_t l0 = f2bf(v.x - bf2f(h0)), l1 = f2bf(v.y - bf2f(h1));
        uint16_t l2 = f2bf(v.z - bf2f(h2)), l3 = f2bf(v.w - bf2f(h3));
        *(uint2*)&Ah[r * A_STRIDE + c4 * 4] = make_uint2(pack2(h0, h1), pack2(h2, h3));
        *(uint2*)&Al[r * A_STRIDE + c4 * 4] = make_uint2(pack2(l0, l1), pack2(l2, l3));
    }
    __syncthreads();

    // ---- main mma loops ----
    float acc[16][4];
    #pragma unroll
    for (int nt = 0; nt < 16; nt++)
        #pragma unroll
        for (int j = 0; j < 4; j++) acc[nt][j] = 0.f;

    int lrow = w * 16 + (lane & 15);
    int lch  = (lane >> 4) & 1;

    for (int ks = 0; ks < 8; ks++) {
        uint32_t ah[4], al[4];
        uint32_t a_h = (uint32_t)__cvta_generic_to_shared(
            &Ah[lrow * A_STRIDE + ks * 16 + lch * 8]);
        uint32_t a_l = (uint32_t)__cvta_generic_to_shared(
            &Al[lrow * A_STRIDE + ks * 16 + lch * 8]);
        LDSM_X4(ah, a_h);
        LDSM_X4(al, a_l);
        #pragma unroll
        for (int nt = 0; nt < 16; nt++) {
            uint2 bh = Wfh[(ks * 16 + nt) * 32 + lane];
            uint2 bl = Wfl[(ks * 16 + nt) * 32 + lane];
            MMA_BF16(acc[nt], ah, bh.x, bh.y);
            MMA_BF16(acc[nt], ah, bl.x, bl.y);
            MMA_BF16(acc[nt], al, bh.x, bh.y);
        }
    }

    // ---- epilogue: bias + relu + store ----
    int r_lo = row0 + w * 16 + g;
    int r_hi = r_lo + 8;
    #pragma unroll
    for (int nt = 0; nt < 16; nt++) {
        int col = nt * 8 + 2 * t;
        float2 bv = *(const float2*)&bias[col];
        if (r_lo < n_rows) {
            float2 o;
            o.x = fmaxf(acc[nt][0] + bv.x, 0.f);
            o.y = fmaxf(acc[nt][1] + bv.y, 0.f);
            *(float2*)&out[(size_t)r_lo * D + col] = o;
        }
        if (r_hi < n_rows) {
            float2 o;
            o.x = fmaxf(acc[nt][2] + bv.x, 0.f);
            o.y = fmaxf(acc[nt][3] + bv.y, 0.f);
            *(float2*)&out[(size_t)r_hi * D + col] = o;
        }
    }
}

// ---------------------------------------------------------------
extern "C" void kernel_launch(void* const* d_in, const int* in_sizes, int n_in,
                              void* d_out, int out_size) {
    const float* x  = (const float*)d_in[0];   // [n_src, 128]
    const int*   ei = (const int*)d_in[1];     // [2, n_edge] int32
    const float* ew = (const float*)d_in[2];   // [n_edge]
    const float* Wm = (const float*)d_in[3];   // [128, 128]
    const float* b  = (const float*)d_in[4];   // [128]
    float* out = (float*)d_out;                // [n_out, 128]

    int n_src  = in_sizes[0] / D;
    int n_edge = in_sizes[2];
    int n_out  = out_size / D;
    int n_tot  = n_src + n_out;
    int nblk   = (n_out + SCAN_CHUNK - 1) / SCAN_CHUNK;
    int e4     = (n_edge + 3) / 4;

    static const int GEMM_SMEM = 2 * 128 * A_STRIDE * 2 + 2 * 4096 * 8; // 135168
    cudaFuncSetAttribute(mma_gemm_kernel,
                         cudaFuncAttributeMaxDynamicSharedMemorySize, GEMM_SMEM);

    init_kernel<<<(n_tot + 255) / 256, 256>>>(Wm, n_tot, n_out);
    degcnt_kernel<<<(e4 + 255) / 256, 256>>>(ei, ew, n_edge, n_tot, n_out);
    scanA_kernel<<<nblk, 1024>>>(n_out);
    scanB_kernel<<<1, 32>>>(nblk, n_out);
    scatter_kernel<<<(e4 + 255) / 256, 256>>>(ei, ew, n_edge, n_tot, n_out);
    gather_kernel<<<(n_out + 7) / 8, 256>>>(x, n_out);
    mma_gemm_kernel<<<(n_out + 127) / 128, 256, GEMM_SMEM>>>(b, out, n_out);
}

// round 8
// speedup vs baseline: 1.0582x; 1.0582x over previous
#include <cuda_runtime.h>
#include <cuda_bf16.h>
#include <cstdint>

#define D 128
#define MAX_N    150016
#define MAX_OUT  50048
#define MAX_E    500000
#define SCAN_CHUNK 4096

// ---- device scratch (static zero-init; each replay re-zeroes what it dirtied
//      so every kernel_launch call sees the same initial state) ----
__device__ float g_deg[MAX_N];          // zeroed by gather tail each run
__device__ int   g_cnt[MAX_OUT];        // zeroed by gather tail each run
__device__ int   g_off[MAX_OUT + 1];    // chunk-LOCAL exclusive offsets
__device__ int   g_cursor[MAX_OUT];     // chunk-LOCAL cursors
__device__ int   g_bsum[64];            // per-chunk totals
__device__ int   g_bpre[64];            // exclusive chunk prefix
__device__ int   g_done;                // scanA completion counter (self-resetting)
__device__ int2  g_epack[MAX_E];        // (row, coef) packed 8B
__device__ float g_agg[(size_t)MAX_OUT * D];
__device__ uint2 g_wf_h[8 * 16 * 32];   // W bf16-hi mma fragments [ks][nt][lane]
__device__ uint2 g_wf_l[8 * 16 * 32];   // W bf16-lo fragments

// ---- helpers ----
__device__ __forceinline__ uint16_t f2bf(float f) {
    __nv_bfloat16 h = __float2bfloat16_rn(f);
    return *reinterpret_cast<uint16_t*>(&h);
}
__device__ __forceinline__ float bf2f(uint16_t u) {
    __nv_bfloat16 h = *reinterpret_cast<__nv_bfloat16*>(&u);
    return __bfloat162float(h);
}
__device__ __forceinline__ uint32_t pack2(uint16_t lo, uint16_t hi) {
    return (uint32_t)lo | ((uint32_t)hi << 16);
}

#define MMA_BF16(ac, a, b0, b1)                                              \
    asm volatile(                                                            \
        "mma.sync.aligned.m16n8k16.row.col.f32.bf16.bf16.f32 "               \
        "{%0,%1,%2,%3}, {%4,%5,%6,%7}, {%8,%9}, {%0,%1,%2,%3};"              \
        : "+f"((ac)[0]), "+f"((ac)[1]), "+f"((ac)[2]), "+f"((ac)[3])         \
        : "r"((a)[0]), "r"((a)[1]), "r"((a)[2]), "r"((a)[3]),                \
          "r"(b0), "r"(b1))

#define LDSM_X4(r, addr)                                                     \
    asm volatile(                                                            \
        "ldmatrix.sync.aligned.m8n8.x4.shared.b16 {%0,%1,%2,%3}, [%4];"      \
        : "=r"((r)[0]), "=r"((r)[1]), "=r"((r)[2]), "=r"((r)[3])             \
        : "r"(addr))

// ---------------------------------------------------------------
// W fragment prep (folded into degcnt_kernel)
// ---------------------------------------------------------------
__device__ __forceinline__ void wprep_one(const float* __restrict__ Wm, int idx) {
    int lane = idx & 31, nt = (idx >> 5) & 15, ks = idx >> 9;
    int g = lane >> 2, t = lane & 3;
    int n  = nt * 8 + g;
    int k0 = ks * 16 + 2 * t;
    float w00 = Wm[(k0 + 0) * D + n];
    float w01 = Wm[(k0 + 1) * D + n];
    float w10 = Wm[(k0 + 8) * D + n];
    float w11 = Wm[(k0 + 9) * D + n];
    uint16_t h00 = f2bf(w00), h01 = f2bf(w01), h10 = f2bf(w10), h11 = f2bf(w11);
    uint16_t l00 = f2bf(w00 - bf2f(h00)), l01 = f2bf(w01 - bf2f(h01));
    uint16_t l10 = f2bf(w10 - bf2f(h10)), l11 = f2bf(w11 - bf2f(h11));
    g_wf_h[idx] = make_uint2(pack2(h00, h01), pack2(h10, h11));
    g_wf_l[idx] = make_uint2(pack2(l00, l01), pack2(l10, l11));
}

// ---------------------------------------------------------------
// K1: degree accumulation (into ZEROED deg; self-loop +1 folded into
//     scatter's rsqrt(1+deg)) + dest histogram + W fragment prep.
//     1 edge/thread, fully coalesced (R6-proven form).
// ---------------------------------------------------------------
__global__ void degcnt_kernel(const int* __restrict__ ei,
                              const float* __restrict__ ew,
                              const float* __restrict__ Wm, int n_edge,
                              int n_tot, int n_out) {
    int e = blockIdx.x * blockDim.x + threadIdx.x;
    if (e < 8 * 16 * 32) wprep_one(Wm, e);
    if (e >= n_edge) return;
    int row = ei[e];
    int col = ei[e + n_edge];
    if ((unsigned)row < (unsigned)n_tot) atomicAdd(&g_deg[row], ew[e]);
    if ((unsigned)col < (unsigned)n_out) atomicAdd(&g_cnt[col], 1);
}

// ---------------------------------------------------------------
// K2: per-chunk LOCAL exclusive scan + fused chunk-prefix
//     (last finishing block computes g_bpre, resets g_done)
// ---------------------------------------------------------------
__global__ __launch_bounds__(1024) void scanA_kernel(int n, int nblk) {
    __shared__ int wsum[32];
    __shared__ int is_last;
    int t = threadIdx.x, lane = t & 31, wid = t >> 5;
    int base = blockIdx.x * SCAN_CHUNK + t * 4;
    int v0 = 0, v1 = 0, v2 = 0, v3 = 0;
    if (base + 3 < n) {
        int4 v = *(const int4*)&g_cnt[base];
        v0 = v.x; v1 = v.y; v2 = v.z; v3 = v.w;
    } else {
        if (base + 0 < n) v0 = g_cnt[base + 0];
        if (base + 1 < n) v1 = g_cnt[base + 1];
        if (base + 2 < n) v2 = g_cnt[base + 2];
        if (base + 3 < n) v3 = g_cnt[base + 3];
    }
    int tin = v0 + v1 + v2 + v3;
    int incl = tin;
    #pragma unroll
    for (int o = 1; o < 32; o <<= 1) {
        int s = __shfl_up_sync(0xffffffffu, incl, o);
        if (lane >= o) incl += s;
    }
    if (lane == 31) wsum[wid] = incl;
    __syncthreads();
    if (wid == 0) {
        int ws = wsum[lane];
        int winc = ws;
        #pragma unroll
        for (int o = 1; o < 32; o <<= 1) {
            int s = __shfl_up_sync(0xffffffffu, winc, o);
            if (lane >= o) winc += s;
        }
        wsum[lane] = winc - ws;
    }
    __syncthreads();
    int texcl = wsum[wid] + incl - tin;
    int e0 = texcl, e1 = e0 + v0, e2 = e1 + v1, e3 = e2 + v2;
    if (base + 0 < n) { g_off[base + 0] = e0; g_cursor[base + 0] = e0; }
    if (base + 1 < n) { g_off[base + 1] = e1; g_cursor[base + 1] = e1; }
    if (base + 2 < n) { g_off[base + 2] = e2; g_cursor[base + 2] = e2; }
    if (base + 3 < n) { g_off[base + 3] = e3; g_cursor[base + 3] = e3; }
    if (n >= base && n <= base + 3) {          // local sentinel at n
        int d = n - base;
        g_off[n] = (d == 0) ? e0 : (d == 1) ? e1 : (d == 2) ? e2 : e3;
    }
    if (t == 1023) g_bsum[blockIdx.x] = wsum[wid] + incl;   // chunk TOTAL

    // ---- fused chunk-prefix: last block to finish computes g_bpre ----
    __syncthreads();
    if (t == 0) {
        __threadfence();
        int old = atomicAdd(&g_done, 1);
        is_last = (old == nblk - 1);
    }
    __syncthreads();
    if (is_last && t < 32) {
        int v = (t < nblk) ? g_bsum[t] : 0;
        int ip = v;
        #pragma unroll
        for (int o = 1; o < 32; o <<= 1) {
            int s = __shfl_up_sync(0xffffffffu, ip, o);
            if (t >= o) ip += s;
        }
        if (t <= nblk) g_bpre[t] = ip - v;
        if (t == 0) {
            g_done = 0;                            // reset for next replay
            if ((n % SCAN_CHUNK) == 0) g_off[n] = 0;  // boundary sentinel
        }
    }
}

// ---------------------------------------------------------------
// K3: CSR placement (1 edge/thread, R6-proven), packed 8B store
//     coef = w_e * rsqrt(1 + deg[row]);  slot = local cursor + prefix
// ---------------------------------------------------------------
__global__ void scatter_kernel(const int* __restrict__ ei,
                               const float* __restrict__ ew, int n_edge,
                               int n_tot, int n_out) {
    int e = blockIdx.x * blockDim.x + threadIdx.x;
    if (e >= n_edge) return;
    int row = ei[e];
    int col = ei[e + n_edge];
    if ((unsigned)row >= (unsigned)n_tot || (unsigned)col >= (unsigned)n_out)
        return;
    float c = ew[e] * rsqrtf(1.0f + g_deg[row]);
    int p = atomicAdd(&g_cursor[col], 1) + g_bpre[col >> 12];
    g_epack[p] = make_int2(row, __float_as_int(c));
}

// ---------------------------------------------------------------
// K4: warp-per-node gather + scratch re-zero for next replay
// ---------------------------------------------------------------
__global__ void gather_kernel(const float* __restrict__ x, int n_out, int n_tot) {
    int gtid = blockIdx.x * blockDim.x + threadIdx.x;
    // re-zero scratch consumed this run (deg used by scatter, cnt by scanA;
    // both strictly before this kernel in stream order)
    if (gtid < n_tot) g_deg[gtid] = 0.0f;
    if (gtid < n_out) g_cnt[gtid] = 0;

    int w = gtid >> 5;
    int lane = threadIdx.x & 31;
    if (w >= n_out) return;
    int s = g_off[w]     + g_bpre[w >> 12];
    int e = g_off[w + 1] + g_bpre[(w + 1) >> 12];
    const float4* x4 = (const float4*)x;
    float4 acc = make_float4(0.f, 0.f, 0.f, 0.f);
    int i = s;
    for (; i + 4 <= e; i += 4) {
        int2 p0 = g_epack[i];
        int2 p1 = g_epack[i + 1];
        int2 p2 = g_epack[i + 2];
        int2 p3 = g_epack[i + 3];
        float4 v0 = x4[(size_t)p0.x * 32 + lane];
        float4 v1 = x4[(size_t)p1.x * 32 + lane];
        float4 v2 = x4[(size_t)p2.x * 32 + lane];
        float4 v3 = x4[(size_t)p3.x * 32 + lane];
        float c0 = __int_as_float(p0.y), c1 = __int_as_float(p1.y);
        float c2 = __int_as_float(p2.y), c3 = __int_as_float(p3.y);
        acc.x += c0 * v0.x + c1 * v1.x + c2 * v2.x + c3 * v3.x;
        acc.y += c0 * v0.y + c1 * v1.y + c2 * v2.y + c3 * v3.y;
        acc.z += c0 * v0.z + c1 * v1.z + c2 * v2.z + c3 * v3.z;
        acc.w += c0 * v0.w + c1 * v1.w + c2 * v2.w + c3 * v3.w;
    }
    for (; i < e; i++) {
        int2 p0 = g_epack[i];
        float4 v0 = x4[(size_t)p0.x * 32 + lane];
        float c0 = __int_as_float(p0.y);
        acc.x += c0 * v0.x; acc.y += c0 * v0.y;
        acc.z += c0 * v0.z; acc.w += c0 * v0.w;
    }
    ((float4*)g_agg)[(size_t)w * 32 + lane] = acc;
}

// ---------------------------------------------------------------
// K5: tensor-core GEMM  out = relu(agg @ W + b)   [R4/R6-proven]
//   block = 128 rows x 128 cols, 8 warps (16 rows each)
//   bf16 2-way split: acc = Ah*Wh + Ah*Wl + Al*Wh  (fp32 accum)
//   smem: Ah/Al (69.6 KB) + staged W fragments (64 KB) = 132 KB
// ---------------------------------------------------------------
#define A_STRIDE 136

__global__ __launch_bounds__(256) void mma_gemm_kernel(const float* __restrict__ bias,
                                                       float* __restrict__ out,
                                                       int n_rows) {
    extern __shared__ char smem[];
    uint16_t* Ah = (uint16_t*)smem;                         // 34816 B
    uint16_t* Al = Ah + 128 * A_STRIDE;                     // +34816 B
    uint2*    Wfh = (uint2*)(smem + 2 * 128 * A_STRIDE * 2);// +32768 B
    uint2*    Wfl = Wfh + 4096;                             // +32768 B

    int tid = threadIdx.x;
    int w = tid >> 5, lane = tid & 31;
    int g = lane >> 2, t = lane & 3;
    int row0 = blockIdx.x * 128;

    // ---- stage W fragments ----
    #pragma unroll
    for (int i = tid; i < 4096; i += 256) {
        Wfh[i] = g_wf_h[i];
        Wfl[i] = g_wf_l[i];
    }

    // ---- stage A: load fp32 agg, split to bf16 hi/lo in smem ----
    #pragma unroll
    for (int i = 0; i < 16; i++) {
        int idx4 = tid + i * 256;          // 0..4095
        int r  = idx4 >> 5;                // 0..127
        int c4 = idx4 & 31;                // 0..31
        float4 v = make_float4(0.f, 0.f, 0.f, 0.f);
        if (row0 + r < n_rows)
            v = *(const float4*)&g_agg[(size_t)(row0 + r) * D + c4 * 4];
        uint16_t h0 = f2bf(v.x), h1 = f2bf(v.y), h2 = f2bf(v.z), h3 = f2bf(v.w);
        uint16_t l0 = f2bf(v.x - bf2f(h0)), l1 = f2bf(v.y - bf2f(h1));
        uint16_t l2 = f2bf(v.z - bf2f(h2)), l3 = f2bf(v.w - bf2f(h3));
        *(uint2*)&Ah[r * A_STRIDE + c4 * 4] = make_uint2(pack2(h0, h1), pack2(h2, h3));
        *(uint2*)&Al[r * A_STRIDE + c4 * 4] = make_uint2(pack2(l0, l1), pack2(l2, l3));
    }
    __syncthreads();

    // ---- main mma loops ----
    float acc[16][4];
    #pragma unroll
    for (int nt = 0; nt < 16; nt++)
        #pragma unroll
        for (int j = 0; j < 4; j++) acc[nt][j] = 0.f;

    int lrow = w * 16 + (lane & 15);
    int lch  = (lane >> 4) & 1;

    for (int ks = 0; ks < 8; ks++) {
        uint32_t ah[4], al[4];
        uint32_t a_h = (uint32_t)__cvta_generic_to_shared(
            &Ah[lrow * A_STRIDE + ks * 16 + lch * 8]);
        uint32_t a_l = (uint32_t)__cvta_generic_to_shared(
            &Al[lrow * A_STRIDE + ks * 16 + lch * 8]);
        LDSM_X4(ah, a_h);
        LDSM_X4(al, a_l);
        #pragma unroll
        for (int nt = 0; nt < 16; nt++) {
            uint2 bh = Wfh[(ks * 16 + nt) * 32 + lane];
            uint2 bl = Wfl[(ks * 16 + nt) * 32 + lane];
            MMA_BF16(acc[nt], ah, bh.x, bh.y);
            MMA_BF16(acc[nt], ah, bl.x, bl.y);
            MMA_BF16(acc[nt], al, bh.x, bh.y);
        }
    }

    // ---- epilogue: bias + relu + store ----
    int r_lo = row0 + w * 16 + g;
    int r_hi = r_lo + 8;
    #pragma unroll
    for (int nt = 0; nt < 16; nt++) {
        int col = nt * 8 + 2 * t;
        float2 bv = *(const float2*)&bias[col];
        if (r_lo < n_rows) {
            float2 o;
            o.x = fmaxf(acc[nt][0] + bv.x, 0.f);
            o.y = fmaxf(acc[nt][1] + bv.y, 0.f);
            *(float2*)&out[(size_t)r_lo * D + col] = o;
        }
        if (r_hi < n_rows) {
            float2 o;
            o.x = fmaxf(acc[nt][2] + bv.x, 0.f);
            o.y = fmaxf(acc[nt][3] + bv.y, 0.f);
            *(float2*)&out[(size_t)r_hi * D + col] = o;
        }
    }
}

// ---------------------------------------------------------------
extern "C" void kernel_launch(void* const* d_in, const int* in_sizes, int n_in,
                              void* d_out, int out_size) {
    const float* x  = (const float*)d_in[0];   // [n_src, 128]
    const int*   ei = (const int*)d_in[1];     // [2, n_edge] int32
    const float* ew = (const float*)d_in[2];   // [n_edge]
    const float* Wm = (const float*)d_in[3];   // [128, 128]
    const float* b  = (const float*)d_in[4];   // [128]
    float* out = (float*)d_out;                // [n_out, 128]

    int n_src  = in_sizes[0] / D;
    int n_edge = in_sizes[2];
    int n_out  = out_size / D;
    int n_tot  = n_src + n_out;
    int nblk   = (n_out + SCAN_CHUNK - 1) / SCAN_CHUNK;

    static const int GEMM_SMEM = 2 * 128 * A_STRIDE * 2 + 2 * 4096 * 8; // 135168
    cudaFuncSetAttribute(mma_gemm_kernel,
                         cudaFuncAttributeMaxDynamicSharedMemorySize, GEMM_SMEM);

    degcnt_kernel<<<(n_edge + 255) / 256, 256>>>(ei, ew, Wm, n_edge, n_tot, n_out);
    scanA_kernel<<<nblk, 1024>>>(n_out, nblk);
    scatter_kernel<<<(n_edge + 255) / 256, 256>>>(ei, ew, n_edge, n_tot, n_out);
    gather_kernel<<<(n_out + 7) / 8, 256>>>(x, n_out, n_tot);
    mma_gemm_kernel<<<(n_out + 127) / 128, 256, GEMM_SMEM>>>(b, out, n_out);
}